// round 6
// baseline (speedup 1.0000x reference)
#include <cuda_runtime.h>
#include <math.h>

// Problem constants
#define N_ROWS   16384
#define NCLS     1000
#define N_ITER   80
// Fixed analytic bracket [-1.375, 1.375] (|v| <= 1.371 provably);
// 2.75 * 2^-32 = 6.4e-10 << ulp(0.34)=3e-8, so nu matches the reference
// root to <= 1 ulp.
#define N_BISECT 32
#define WPB      8          // warps (rows) per block
#define FULLJ    31         // j=0..30 cover elems 0..991
#define TAILCNT  (NCLS - FULLJ*32)  // 8 lanes own a 32nd element

__device__ float g_row_loss[N_ROWS];

__global__ __launch_bounds__(32*WPB)
void pgd_kernel(const float* __restrict__ x, const int* __restrict__ y)
{
    const int warp = threadIdx.x >> 5;
    const int lane = threadIdx.x & 31;
    const int row  = blockIdx.x * WPB + warp;

    const float* __restrict__ xr = x + (size_t)row * NCLS;
    const bool tail = lane < TAILCNT;

    // ---- load row (coalesced: elem = j*32 + lane) ----
    float c[32];
#pragma unroll
    for (int j = 0; j < FULLJ; ++j) c[j] = xr[j*32 + lane];
    c[FULLJ] = tail ? xr[FULLJ*32 + lane] : 0.0f;

    // ---- L2 normalize, folding alpha: c <- alpha * x / norm ----
    float ss = 0.0f;
#pragma unroll
    for (int j = 0; j < 32; ++j) ss = fmaf(c[j], c[j], ss);
#pragma unroll
    for (int o = 16; o; o >>= 1) ss += __shfl_xor_sync(0xffffffffu, ss, o);
    const float scl = __fdiv_rn(0.025f, fmaxf(sqrtf(ss), 1e-12f));
#pragma unroll
    for (int j = 0; j < 32; ++j) c[j] *= scl;

    // p held implicitly as sat(v - nu); init p = k/n = 0.005.
    // Lanes without a tail element park v[31] at -1e30: in the projection sum
    // max(-1e30, mid) == mid, which the per-accumulator 8*mid base cancels.
    float v[32];
#pragma unroll
    for (int j = 0; j < FULLJ; ++j) v[j] = 0.005f;
    v[FULLJ] = tail ? 0.005f : -1e30f;
    float nu = 0.0f;

    const float PC_LO = 1e-6f;
    const float PC_HI = 1.0f - 1e-6f;
    const float C1    = 0.025f * 0.69314718055994531f;   // alpha * ln2

    for (int it = 0; it < N_ITER; ++it) {
        // ---- gradient step: v = p + alpha*c + alpha*ln2*(lg2(1-pc)-lg2(pc)) ----
#pragma unroll
        for (int j = 0; j < 32; ++j) {
            float p  = __saturatef(v[j] - nu);
            float pc = fminf(fmaxf(p, PC_LO), PC_HI);
            float d  = __log2f(1.0f - pc) - __log2f(pc);
            float nv = fmaf(C1, d, p + c[j]);
            v[j] = (j < FULLJ || tail) ? nv : -1e30f;
        }

        // ---- capped-simplex projection: bisection on nu over a fixed
        //      analytic bracket. Key identity:
        //        sum_j sat(v_j - mid) == sum_j max(v_j, mid) - n*mid
        //      (saturate-at-1 never changes a bisection decision: it can only
        //      bind when mid <= vmax-1 < root, where the true sum is > k).
        //      max() is FMNMX on the ALU pipe, halving fma-pipe load.
        float lo = -1.375f;
        float hi =  1.375f;
        for (int b = 0; b < N_BISECT; ++b) {
            const float mid = 0.5f * (lo + hi);
            float s0 = 0.f, s1 = 0.f, s2 = 0.f, s3 = 0.f;
#pragma unroll
            for (int j = 0; j < 32; j += 4) {
                s0 += fmaxf(v[j+0], mid);
                s1 += fmaxf(v[j+1], mid);
                s2 += fmaxf(v[j+2], mid);
                s3 += fmaxf(v[j+3], mid);
            }
            // subtract the 8*mid base per accumulator while magnitudes are
            // small (<= 11), keeping cancellation noise sub-ulp in nu
            s0 = fmaf(-8.0f, mid, s0);
            s1 = fmaf(-8.0f, mid, s1);
            s2 = fmaf(-8.0f, mid, s2);
            s3 = fmaf(-8.0f, mid, s3);
            float s = (s0 + s1) + (s2 + s3);
#pragma unroll
            for (int o = 16; o; o >>= 1) s += __shfl_xor_sync(0xffffffffu, s, o);
            const bool big = s > 5.0f;
            lo = big ? mid : lo;
            hi = big ? hi  : mid;
        }
        nu = 0.5f * (lo + hi);
    }

    // ---- p_y = clip(v[y] - nu, 0, 1); loss = -log(p_y + 1e-8) ----
    const int yi = y[row];
    float py = 0.0f;
#pragma unroll
    for (int j = 0; j < 32; ++j) {
        if (j*32 + lane == yi) py = __saturatef(v[j] - nu);
    }
#pragma unroll
    for (int o = 16; o; o >>= 1) py += __shfl_xor_sync(0xffffffffu, py, o);

    if (lane == 0) g_row_loss[row] = -logf(py + 1e-8f);
}

__global__ void reduce_kernel(float* __restrict__ out)
{
    __shared__ float sh[8];
    float s = 0.0f;
    for (int i = threadIdx.x; i < N_ROWS; i += 256) s += g_row_loss[i];
#pragma unroll
    for (int o = 16; o; o >>= 1) s += __shfl_xor_sync(0xffffffffu, s, o);
    const int w = threadIdx.x >> 5;
    const int l = threadIdx.x & 31;
    if (l == 0) sh[w] = s;
    __syncthreads();
    if (threadIdx.x == 0) {
        float t = 0.0f;
#pragma unroll
        for (int i = 0; i < 8; ++i) t += sh[i];
        out[0] = t * (1.0f / (float)N_ROWS);
    }
}

extern "C" void kernel_launch(void* const* d_in, const int* in_sizes, int n_in,
                              void* d_out, int out_size)
{
    const float* x = (const float*)d_in[0];
    const int*   y = (const int*)d_in[1];
    pgd_kernel<<<N_ROWS / WPB, 32 * WPB>>>(x, y);
    reduce_kernel<<<1, 256>>>((float*)d_out);
}

// round 14
// speedup vs baseline: 1.2443x; 1.2443x over previous
#include <cuda_runtime.h>
#include <math.h>

// Problem constants
#define N_ROWS   16384
#define NCLS     1000
#define N_ITER   80
#define N_COARSE 15
#define N_FINE   15         // total 30: width <= 2.745*2^-30 = 2.6e-9 < 1 ulp of nu
#define BANDCAP  96
#define WPB      8          // warps (rows) per block
#define FULLJ    31         // j=0..30 cover elems 0..991
#define TAILCNT  (NCLS - FULLJ*32)  // 8 lanes own a 32nd element

__device__ float g_row_loss[N_ROWS];

__global__ __launch_bounds__(32*WPB)
void pgd_kernel(const float* __restrict__ x, const int* __restrict__ y)
{
    __shared__ float sh_band[WPB][BANDCAP];

    const int warp = threadIdx.x >> 5;
    const int lane = threadIdx.x & 31;
    const int row  = blockIdx.x * WPB + warp;
    const unsigned FULL = 0xffffffffu;
    const unsigned lt_mask = (1u << lane) - 1u;

    const float* __restrict__ xr = x + (size_t)row * NCLS;
    const bool tail = lane < TAILCNT;

    // ---- load row (coalesced: elem = j*32 + lane) ----
    float c[32];
#pragma unroll
    for (int j = 0; j < FULLJ; ++j) c[j] = xr[j*32 + lane];
    c[FULLJ] = tail ? xr[FULLJ*32 + lane] : 0.0f;

    // ---- L2 normalize, folding alpha: c <- alpha * x / norm ----
    float ss = 0.0f;
#pragma unroll
    for (int j = 0; j < 32; ++j) ss = fmaf(c[j], c[j], ss);
#pragma unroll
    for (int o = 16; o; o >>= 1) ss += __shfl_xor_sync(FULL, ss, o);
    const float scl = __fdiv_rn(0.025f, fmaxf(sqrtf(ss), 1e-12f));
#pragma unroll
    for (int j = 0; j < 32; ++j) c[j] *= scl;

    // p held implicitly as sat(v - nu); init p = k/n = 0.005
    float v[32];
    float nu = 0.0f;
#pragma unroll
    for (int j = 0; j < 32; ++j) v[j] = 0.005f;

    const float PC_LO = 1e-6f;
    const float PC_HI = 1.0f - 1e-6f;
    const float C1    = 0.025f * 0.69314718055994531f;   // alpha * ln2

    for (int it = 0; it < N_ITER; ++it) {
        // ---- gradient step: v = p + alpha*c + alpha*ln2*(lg2(1-pc)-lg2(pc)) ----
        float vmin =  1e30f;
        float vmax = -1e30f;
#pragma unroll
        for (int j = 0; j < 32; ++j) {
            if (j < FULLJ || tail) {
                float p  = __saturatef(v[j] - nu);
                float pc = fminf(fmaxf(p, PC_LO), PC_HI);
                float d  = __log2f(1.0f - pc) - __log2f(pc);
                float nv = fmaf(C1, d, p + c[j]);
                v[j] = nv;
                vmin = fminf(vmin, nv);
                vmax = fmaxf(vmax, nv);
            }
        }
#pragma unroll
        for (int o = 16; o; o >>= 1) {
            vmin = fminf(vmin, __shfl_xor_sync(FULL, vmin, o));
            vmax = fmaxf(vmax, __shfl_xor_sync(FULL, vmax, o));
        }

        // ---- Phase 1: coarse bisection, full evals (R5-exact form) ----
        float lo = vmin - 1.0f;
        float hi = vmax;
        for (int b = 0; b < N_COARSE; ++b) {
            const float mid = 0.5f * (lo + hi);
            float s0 = 0.f, s1 = 0.f, s2 = 0.f, s3 = 0.f;
#pragma unroll
            for (int j = 0; j < 28; j += 4) {
                s0 += __saturatef(v[j+0] - mid);
                s1 += __saturatef(v[j+1] - mid);
                s2 += __saturatef(v[j+2] - mid);
                s3 += __saturatef(v[j+3] - mid);
            }
            s0 += __saturatef(v[28] - mid);
            s1 += __saturatef(v[29] - mid);
            s2 += __saturatef(v[30] - mid);
            if (tail) s3 += __saturatef(v[31] - mid);
            float s = (s0 + s1) + (s2 + s3);
#pragma unroll
            for (int o = 16; o; o >>= 1) s += __shfl_xor_sync(FULL, s, o);
            const bool big = s > 5.0f;
            lo = big ? mid : lo;
            hi = big ? hi  : mid;
        }

        // ---- Classify elements against the frozen bracket [lo0, hi0] ----
        // For any mid in (lo0, hi0):
        //   v <= lo0            -> 0
        //   lo0 < v <= hi0      -> band (needs sat(v - mid))
        //   hi0 < v <= lo0+1    -> linear: contributes (v - hi0) + (hi0 - mid)
        //   lo0+1 < v <= hi0+1  -> band (sat handles crossing 1)
        //   v > hi0+1           -> contributes exactly 1
        const float lo0 = lo, hi0 = hi;
        const float tl1 = lo0 + 1.0f;
        const float th1 = hi0 + 1.0f;
        float slin = 0.0f, nlin = 0.0f, nsat = 0.0f;
        int base = 0;
#pragma unroll
        for (int j = 0; j < 32; ++j) {
            const bool valid = (j < FULLJ) || tail;
            const float vj = v[j];
            const bool gLo = vj > lo0;
            const bool gHi = vj > hi0;
            const bool gL1 = vj > tl1;
            const bool gH1 = vj > th1;
            const bool band = valid && ((gLo && !gHi) || (gL1 && !gH1));
            if (valid && gHi && !gL1) { slin += vj - hi0; nlin += 1.0f; }
            if (valid && gH1)         { nsat += 1.0f; }
            const unsigned m = __ballot_sync(FULL, band);
            if (band) {
                const int pos = base + __popc(m & lt_mask);
                if (pos < BANDCAP) sh_band[warp][pos] = vj;
            }
            base += __popc(m);
        }
#pragma unroll
        for (int o = 16; o; o >>= 1) {
            slin += __shfl_xor_sync(FULL, slin, o);
            nlin += __shfl_xor_sync(FULL, nlin, o);
            nsat += __shfl_xor_sync(FULL, nsat, o);
        }
        __syncwarp();
        const bool cheap = (base <= BANDCAP);
        const float r0 = (lane      < base && cheap) ? sh_band[warp][lane]      : -1e30f;
        const float r1 = (lane + 32 < base && cheap) ? sh_band[warp][lane + 32] : -1e30f;
        const float r2 = (lane + 64 < base && cheap) ? sh_band[warp][lane + 64] : -1e30f;
        const float s_base = nsat;          // constant part

        // ---- Phase 2: fine bisection on the band + affine remainder ----
        for (int b = 0; b < N_FINE; ++b) {
            const float mid = 0.5f * (lo + hi);
            float s;
            if (cheap) {
                float sb = __saturatef(r0 - mid) + __saturatef(r1 - mid)
                         + __saturatef(r2 - mid);
#pragma unroll
                for (int o = 16; o; o >>= 1) sb += __shfl_xor_sync(FULL, sb, o);
                s = sb + s_base + fmaf(nlin, hi0 - mid, slin);
            } else {
                float s0 = 0.f, s1 = 0.f, s2 = 0.f, s3 = 0.f;
#pragma unroll
                for (int j = 0; j < 28; j += 4) {
                    s0 += __saturatef(v[j+0] - mid);
                    s1 += __saturatef(v[j+1] - mid);
                    s2 += __saturatef(v[j+2] - mid);
                    s3 += __saturatef(v[j+3] - mid);
                }
                s0 += __saturatef(v[28] - mid);
                s1 += __saturatef(v[29] - mid);
                s2 += __saturatef(v[30] - mid);
                if (tail) s3 += __saturatef(v[31] - mid);
                s = (s0 + s1) + (s2 + s3);
#pragma unroll
                for (int o = 16; o; o >>= 1) s += __shfl_xor_sync(FULL, s, o);
            }
            const bool big = s > 5.0f;
            lo = big ? mid : lo;
            hi = big ? hi  : mid;
        }
        nu = 0.5f * (lo + hi);
    }

    // ---- p_y = clip(v[y] - nu, 0, 1); loss = -log(p_y + 1e-8) ----
    const int yi = y[row];
    float py = 0.0f;
#pragma unroll
    for (int j = 0; j < 32; ++j) {
        if (j*32 + lane == yi) py = __saturatef(v[j] - nu);
    }
#pragma unroll
    for (int o = 16; o; o >>= 1) py += __shfl_xor_sync(FULL, py, o);

    if (lane == 0) g_row_loss[row] = -logf(py + 1e-8f);
}

__global__ void reduce_kernel(float* __restrict__ out)
{
    __shared__ float sh[8];
    float s = 0.0f;
    for (int i = threadIdx.x; i < N_ROWS; i += 256) s += g_row_loss[i];
#pragma unroll
    for (int o = 16; o; o >>= 1) s += __shfl_xor_sync(0xffffffffu, s, o);
    const int w = threadIdx.x >> 5;
    const int l = threadIdx.x & 31;
    if (l == 0) sh[w] = s;
    __syncthreads();
    if (threadIdx.x == 0) {
        float t = 0.0f;
#pragma unroll
        for (int i = 0; i < 8; ++i) t += sh[i];
        out[0] = t * (1.0f / (float)N_ROWS);
    }
}

extern "C" void kernel_launch(void* const* d_in, const int* in_sizes, int n_in,
                              void* d_out, int out_size)
{
    const float* x = (const float*)d_in[0];
    const int*   y = (const int*)d_in[1];
    pgd_kernel<<<N_ROWS / WPB, 32 * WPB>>>(x, y);
    reduce_kernel<<<1, 256>>>((float*)d_out);
}

// round 15
// speedup vs baseline: 1.2810x; 1.0295x over previous
#include <cuda_runtime.h>
#include <math.h>

// Problem constants
#define N_ROWS   16384
#define NCLS     1000
#define N_ITER   80
#define N_BISECT 30         // bracket <= 2.75 * 2^-30 = 2.6e-9 < 1 ulp of nu
#define WPB      8          // warps (rows) per block
#define FULLJ    31         // j=0..30 cover elems 0..991
#define TAILCNT  (NCLS - FULLJ*32)  // 8 lanes own a 32nd element
#define NF       19         // elements j=0..18: float path (fma pipe)
#define NI       13         // elements j=19..31: int path (alu pipe)
#define FPSCALE  16777216.0f           // 2^24
#define INV_FPS  (1.0f/16777216.0f)

__device__ float g_row_loss[N_ROWS];

__global__ __launch_bounds__(32*WPB)
void pgd_kernel(const float* __restrict__ x, const int* __restrict__ y)
{
    const int warp = threadIdx.x >> 5;
    const int lane = threadIdx.x & 31;
    const int row  = blockIdx.x * WPB + warp;
    const unsigned FULL = 0xffffffffu;

    const float* __restrict__ xr = x + (size_t)row * NCLS;
    const bool tail = lane < TAILCNT;

    // ---- load row (coalesced: elem = j*32 + lane) ----
    float c[32];
#pragma unroll
    for (int j = 0; j < FULLJ; ++j) c[j] = xr[j*32 + lane];
    c[FULLJ] = tail ? xr[FULLJ*32 + lane] : 0.0f;

    // ---- L2 normalize, folding alpha: c <- alpha * x / norm ----
    float ss = 0.0f;
#pragma unroll
    for (int j = 0; j < 32; ++j) ss = fmaf(c[j], c[j], ss);
#pragma unroll
    for (int o = 16; o; o >>= 1) ss += __shfl_xor_sync(FULL, ss, o);
    const float scl = __fdiv_rn(0.025f, fmaxf(sqrtf(ss), 1e-12f));
#pragma unroll
    for (int j = 0; j < 32; ++j) c[j] *= scl;

    // p held implicitly as sat(v - nu); init p = k/n = 0.005
    float v[32];
    float nu = 0.0f;
#pragma unroll
    for (int j = 0; j < 32; ++j) v[j] = 0.005f;

    const float PC_LO = 1e-6f;
    const float PC_HI = 1.0f - 1e-6f;
    const float C1    = 0.025f * 0.69314718055994531f;   // alpha * ln2

    for (int it = 0; it < N_ITER; ++it) {
        // ---- gradient step: v = p + alpha*c + alpha*ln2*(lg2(1-pc)-lg2(pc)) ----
        float vmin =  1e30f;
        float vmax = -1e30f;
#pragma unroll
        for (int j = 0; j < 32; ++j) {
            if (j < FULLJ || tail) {
                float p  = __saturatef(v[j] - nu);
                float pc = fminf(fmaxf(p, PC_LO), PC_HI);
                float d  = __log2f(1.0f - pc) - __log2f(pc);
                float nv = fmaf(C1, d, p + c[j]);
                v[j] = nv;
                vmin = fminf(vmin, nv);
                vmax = fmaxf(vmax, nv);
            }
        }
#pragma unroll
        for (int o = 16; o; o >>= 1) {
            vmin = fminf(vmin, __shfl_xor_sync(FULL, vmin, o));
            vmax = fmaxf(vmax, __shfl_xor_sync(FULL, vmax, o));
        }

        // ---- mirror elements j=19..31 into fixed-point int32 (scale 2^24).
        // Invalid tail slots park at a huge negative so max(d,0)==0 always.
        int vi[NI];
#pragma unroll
        for (int jj = 0; jj < NI; ++jj) {
            const bool valid = (jj < NI-1) || tail;           // j=19+jj; j<31 always valid
            vi[jj] = valid ? __float2int_rn(v[NF + jj] * FPSCALE)
                           : (int)0xC0000000;                  // -2^30
        }

        // ---- capped-simplex projection: bisection on nu.
        // Sum split across pipes:
        //   float part (fma pipe):  sum_{j<19} sat(v_j - mid)
        //   int part   (alu pipe):  sum_{j>=19} max(v_j - mid, 0)  [fixed point]
        // Dropping the saturate-at-1 on the int part never changes a decision:
        // it binds only when mid <= vmax-1 < root, where the true sum > k
        // (validated bit-exact in an earlier round with the identity global).
        float lo = vmin - 1.0f;
        float hi = vmax;
        for (int b = 0; b < N_BISECT; ++b) {
            const float mid  = 0.5f * (lo + hi);
            const int   midi = __float2int_rn(mid * FPSCALE);

            float s0 = 0.f, s1 = 0.f, s2 = 0.f;
#pragma unroll
            for (int j = 0; j < 18; j += 3) {
                s0 += __saturatef(v[j+0] - mid);
                s1 += __saturatef(v[j+1] - mid);
                s2 += __saturatef(v[j+2] - mid);
            }
            s0 += __saturatef(v[18] - mid);

            int ia = 0, ib = 0;
#pragma unroll
            for (int jj = 0; jj < 12; jj += 2) {
                ia += max(vi[jj+0] - midi, 0);
                ib += max(vi[jj+1] - midi, 0);
            }
            ia += max(vi[12] - midi, 0);

            float s = (s0 + s1) + fmaf(__int2float_rn(ia + ib), INV_FPS, s2);
#pragma unroll
            for (int o = 16; o; o >>= 1) s += __shfl_xor_sync(FULL, s, o);
            const bool big = s > 5.0f;
            lo = big ? mid : lo;
            hi = big ? hi  : mid;
        }
        nu = 0.5f * (lo + hi);
    }

    // ---- p_y = clip(v[y] - nu, 0, 1); loss = -log(p_y + 1e-8) ----
    const int yi = y[row];
    float py = 0.0f;
#pragma unroll
    for (int j = 0; j < 32; ++j) {
        if (j*32 + lane == yi) py = __saturatef(v[j] - nu);
    }
#pragma unroll
    for (int o = 16; o; o >>= 1) py += __shfl_xor_sync(FULL, py, o);

    if (lane == 0) g_row_loss[row] = -logf(py + 1e-8f);
}

__global__ void reduce_kernel(float* __restrict__ out)
{
    __shared__ float sh[8];
    float s = 0.0f;
    for (int i = threadIdx.x; i < N_ROWS; i += 256) s += g_row_loss[i];
#pragma unroll
    for (int o = 16; o; o >>= 1) s += __shfl_xor_sync(0xffffffffu, s, o);
    const int w = threadIdx.x >> 5;
    const int l = threadIdx.x & 31;
    if (l == 0) sh[w] = s;
    __syncthreads();
    if (threadIdx.x == 0) {
        float t = 0.0f;
#pragma unroll
        for (int i = 0; i < 8; ++i) t += sh[i];
        out[0] = t * (1.0f / (float)N_ROWS);
    }
}

extern "C" void kernel_launch(void* const* d_in, const int* in_sizes, int n_in,
                              void* d_out, int out_size)
{
    const float* x = (const float*)d_in[0];
    const int*   y = (const int*)d_in[1];
    pgd_kernel<<<N_ROWS / WPB, 32 * WPB>>>(x, y);
    reduce_kernel<<<1, 256>>>((float*)d_out);
}